// round 8
// baseline (speedup 1.0000x reference)
#include <cuda_runtime.h>
#include <cuda_fp16.h>
#include <cstdint>
#include <stdint.h>
#include <math.h>

#define N 8192
#define D 128
#define TILE 128
#define NB (N / TILE)             // 64
#define NTRI (NB * (NB + 1) / 2)  // 2080 upper-tri tiles
#define NCTA 296                  // 148 SMs x 2 resident CTAs (all co-resident)
#define LDH 136                   // padded SMEM stride, LDSM conflict-free
#define WEIGHT 0.01f

// ---------------------------------------------------------------------------
// Device scratch
// ---------------------------------------------------------------------------
__device__ __half   g_fh[N * D];
__device__ float    g_suffix[N];
__device__ float    g_prefix[N];
__device__ float    g_pos[N];
__device__ unsigned g_sync1;   // normalize barrier (reset by last CTA)
__device__ unsigned g_sync2;   // done counter     (reset by last CTA)

// ---------------------------------------------------------------------------
__device__ __forceinline__ void mma16816(float* c,
    uint32_t a0, uint32_t a1, uint32_t a2, uint32_t a3,
    uint32_t b0, uint32_t b1)
{
    asm volatile(
        "mma.sync.aligned.m16n8k16.row.col.f32.f16.f16.f32 "
        "{%0,%1,%2,%3}, {%4,%5,%6,%7}, {%8,%9}, {%0,%1,%2,%3};"
        : "+f"(c[0]), "+f"(c[1]), "+f"(c[2]), "+f"(c[3])
        : "r"(a0), "r"(a1), "r"(a2), "r"(a3), "r"(b0), "r"(b1));
}

__device__ __forceinline__ void ldsm_x4(uint32_t& r0, uint32_t& r1,
                                        uint32_t& r2, uint32_t& r3, uint32_t a) {
    asm volatile("ldmatrix.sync.aligned.m8n8.x4.shared.b16 {%0,%1,%2,%3}, [%4];"
                 : "=r"(r0), "=r"(r1), "=r"(r2), "=r"(r3) : "r"(a));
}
__device__ __forceinline__ void ldsm_x2(uint32_t& r0, uint32_t& r1, uint32_t a) {
    asm volatile("ldmatrix.sync.aligned.m8n8.x2.shared.b16 {%0,%1}, [%2];"
                 : "=r"(r0), "=r"(r1) : "r"(a));
}

__device__ __forceinline__ uint32_t smem_u32(const void* p) {
    uint32_t a;
    asm("{ .reg .u64 t; cvta.to.shared.u64 t, %1; cvt.u32.u64 %0, t; }"
        : "=r"(a) : "l"(p));
    return a;
}

#define CP_COMMIT()   asm volatile("cp.async.commit_group;" ::: "memory")
#define CP_WAIT_ALL() asm volatile("cp.async.wait_all;" ::: "memory")

__device__ __forceinline__ void prefetch_tile(uint32_t dst_s,
                                              const __half* __restrict__ src,
                                              int tid) {
#pragma unroll
    for (int it = 0; it < 8; it++) {
        int idx = tid + it * 256;
        int row = idx >> 4;
        int ch  = idx & 15;
        uint32_t d = dst_s + (uint32_t)(row * LDH + ch * 8) * 2u;
        const void* s = src + row * D + ch * 8;
        asm volatile("cp.async.cg.shared.global [%0], [%1], 16;"
                     :: "r"(d), "l"(s) : "memory");
    }
}

// ---------------------------------------------------------------------------
// Single fused kernel: normalize -> grid barrier -> gram tiles -> last-CTA lse
// ---------------------------------------------------------------------------
#define SMEM_BYTES (TILE * LDH * 2 + 2 * TILE * LDH * 2 + 2 * TILE * 4)

__global__ __launch_bounds__(256, 2) void fused_kernel(
    const float* __restrict__ in, float* __restrict__ out)
{
    extern __shared__ char smem[];
    __half* As  = (__half*)smem;
    __half* Bs0 = As + TILE * LDH;
    __half* Bs1 = Bs0 + TILE * LDH;
    float*  s_row = (float*)(Bs1 + TILE * LDH);
    float*  s_col = s_row + TILE;

    const int tid  = threadIdx.x;
    const int wid  = tid >> 5;
    const int lane = tid & 31;
    const int wrow = wid >> 2;
    const int wcol = wid & 3;
    const int g    = lane >> 2;
    const int tg   = lane & 3;

    // ===== Phase 0: normalize my slice of rows; zero accumulators =====
    for (int row = blockIdx.x * 8 + wid; row < N; row += NCTA * 8) {
        float4 v = ((const float4*)(in + (size_t)row * D))[lane];
        float ss = v.x * v.x + v.y * v.y + v.z * v.z + v.w * v.w;
#pragma unroll
        for (int o = 16; o > 0; o >>= 1) ss += __shfl_xor_sync(0xffffffffu, ss, o);
        float scale = 1.0f / fmaxf(sqrtf(ss), 1e-12f);
        __half2 h0 = __floats2half2_rn(v.x * scale, v.y * scale);
        __half2 h1 = __floats2half2_rn(v.z * scale, v.w * scale);
        ((__half2*)(g_fh + (size_t)row * D))[lane * 2 + 0] = h0;
        ((__half2*)(g_fh + (size_t)row * D))[lane * 2 + 1] = h1;
    }
    {
        int r = blockIdx.x * 256 + tid;
        if (r < N) { g_suffix[r] = 0.0f; g_prefix[r] = 0.0f; }
    }
    __syncthreads();

    // ===== Grid barrier (all 296 CTAs are co-resident) =====
    if (tid == 0) {
        __threadfence();
        atomicAdd(&g_sync1, 1u);
        unsigned v;
        do {
            asm volatile("ld.volatile.global.u32 %0, [%1];" : "=r"(v)
                         : "l"(&g_sync1));
            if (v < NCTA) __nanosleep(64);
        } while (v < NCTA);
    }
    __syncthreads();
    __threadfence();

    // ===== Phase 1: persistent gram over my triangular slice =====
    const uint32_t As_s  = smem_u32(As);
    const uint32_t Bs_s0 = smem_u32(Bs0);
    const uint32_t Bs_s1 = smem_u32(Bs1);
    const uint32_t aoff = (uint32_t)((lane & 15) * LDH + (lane >> 4) * 8) * 2u;
    const uint32_t boff = (uint32_t)((lane & 7) * LDH + ((lane >> 3) & 1) * 8) * 2u;

    const int lo = (int)(((long long)blockIdx.x * NTRI) / NCTA);
    const int hi = (int)(((long long)(blockIdx.x + 1) * NTRI) / NCTA);

    int I = 0;
    while ((I + 1) * NB - (I + 1) * I / 2 <= lo) ++I;
    {
        const int J0 = I + (lo - (I * NB - I * (I - 1) / 2));
        prefetch_tile(As_s, g_fh + (size_t)I * TILE * D, tid);
        prefetch_tile(Bs_s0, g_fh + (size_t)J0 * TILE * D, tid);
        CP_COMMIT();
    }

    int buf = 0;
    for (int t = lo; t < hi; ++t) {
        while ((I + 1) * NB - (I + 1) * I / 2 <= t) ++I;
        const int J = I + (t - (I * NB - I * (I - 1) / 2));

        int In = I, Jn = 0;
        const bool have_next = (t + 1 < hi);
        if (have_next) {
            while ((In + 1) * NB - (In + 1) * In / 2 <= t + 1) ++In;
            Jn = In + ((t + 1) - (In * NB - In * (In - 1) / 2));
        }

        CP_WAIT_ALL();
        __syncthreads();

        if (tid < TILE) s_row[tid] = 0.0f;
        else            s_col[tid - TILE] = 0.0f;

        if (have_next)
            prefetch_tile(buf ? Bs_s0 : Bs_s1, g_fh + (size_t)Jn * TILE * D, tid);
        CP_COMMIT();
        __syncthreads();

        const uint32_t Acur = As_s + aoff;
        const uint32_t Bcur = (buf ? Bs_s1 : Bs_s0) + boff;

        float acc[4][4][4];
#pragma unroll
        for (int mt = 0; mt < 4; mt++)
#pragma unroll
            for (int nt = 0; nt < 4; nt++)
#pragma unroll
                for (int e = 0; e < 4; e++) acc[mt][nt][e] = 0.0f;

#pragma unroll
        for (int k0 = 0; k0 < D; k0 += 16) {
            uint32_t bfr[4][2];
#pragma unroll
            for (int nt = 0; nt < 4; nt++)
                ldsm_x2(bfr[nt][0], bfr[nt][1],
                        Bcur + (uint32_t)((wcol * 32 + nt * 8) * LDH + k0) * 2u);
#pragma unroll
            for (int mt = 0; mt < 4; mt++) {
                uint32_t a0, a1, a2, a3;
                ldsm_x4(a0, a1, a2, a3,
                        Acur + (uint32_t)((wrow * 64 + mt * 16) * LDH + k0) * 2u);
#pragma unroll
                for (int nt = 0; nt < 4; nt++)
                    mma16816(acc[mt][nt], a0, a1, a2, a3, bfr[nt][0], bfr[nt][1]);
            }
        }

        // --- Epilogue ---
        float csum[4][2];
#pragma unroll
        for (int nt = 0; nt < 4; nt++) { csum[nt][0] = 0.0f; csum[nt][1] = 0.0f; }

        if (J > I + 1) {
#pragma unroll
            for (int mt = 0; mt < 4; mt++) {
                float rs0 = 0.0f, rs1 = 0.0f;
#pragma unroll
                for (int nt = 0; nt < 4; nt++) {
                    float e00 = __expf(acc[mt][nt][0]);
                    float e01 = __expf(acc[mt][nt][1]);
                    float e10 = __expf(acc[mt][nt][2]);
                    float e11 = __expf(acc[mt][nt][3]);
                    rs0 += e00 + e01;
                    rs1 += e10 + e11;
                    csum[nt][0] += e00 + e10;
                    csum[nt][1] += e01 + e11;
                }
                rs0 += __shfl_xor_sync(0xffffffffu, rs0, 1);
                rs0 += __shfl_xor_sync(0xffffffffu, rs0, 2);
                rs1 += __shfl_xor_sync(0xffffffffu, rs1, 1);
                rs1 += __shfl_xor_sync(0xffffffffu, rs1, 2);
                if (tg == 0) {
                    atomicAdd(&s_row[wrow * 64 + mt * 16 + g], rs0);
                    atomicAdd(&s_row[wrow * 64 + mt * 16 + g + 8], rs1);
                }
            }
        } else {
#pragma unroll
            for (int mt = 0; mt < 4; mt++) {
                const int gi0 = I * TILE + wrow * 64 + mt * 16 + g;
                const int gi1 = gi0 + 8;
                float rs0 = 0.0f, rs1 = 0.0f;
#pragma unroll
                for (int nt = 0; nt < 4; nt++) {
                    const int gj0 = J * TILE + wcol * 32 + nt * 8 + tg * 2;
                    const int gj1 = gj0 + 1;
                    float e00 = (gj0 > gi0) ? __expf(acc[mt][nt][0]) : 0.0f;
                    float e01 = (gj1 > gi0) ? __expf(acc[mt][nt][1]) : 0.0f;
                    float e10 = (gj0 > gi1) ? __expf(acc[mt][nt][2]) : 0.0f;
                    float e11 = (gj1 > gi1) ? __expf(acc[mt][nt][3]) : 0.0f;
                    rs0 += e00 + e01;
                    rs1 += e10 + e11;
                    csum[nt][0] += ((gj0 >= gi0 + 2) ? e00 : 0.0f) + ((gj0 >= gi1 + 2) ? e10 : 0.0f);
                    csum[nt][1] += ((gj1 >= gi0 + 2) ? e01 : 0.0f) + ((gj1 >= gi1 + 2) ? e11 : 0.0f);
                    if (gj0 == gi0 + 1) g_pos[gi0] = acc[mt][nt][0];
                    if (gj1 == gi0 + 1) g_pos[gi0] = acc[mt][nt][1];
                    if (gj0 == gi1 + 1) g_pos[gi1] = acc[mt][nt][2];
                    if (gj1 == gi1 + 1) g_pos[gi1] = acc[mt][nt][3];
                }
                rs0 += __shfl_xor_sync(0xffffffffu, rs0, 1);
                rs0 += __shfl_xor_sync(0xffffffffu, rs0, 2);
                rs1 += __shfl_xor_sync(0xffffffffu, rs1, 1);
                rs1 += __shfl_xor_sync(0xffffffffu, rs1, 2);
                if (tg == 0) {
                    atomicAdd(&s_row[wrow * 64 + mt * 16 + g], rs0);
                    atomicAdd(&s_row[wrow * 64 + mt * 16 + g + 8], rs1);
                }
            }
        }

#pragma unroll
        for (int nt = 0; nt < 4; nt++) {
#pragma unroll
            for (int e = 0; e < 2; e++) {
                float v = csum[nt][e];
                v += __shfl_xor_sync(0xffffffffu, v, 4);
                v += __shfl_xor_sync(0xffffffffu, v, 8);
                v += __shfl_xor_sync(0xffffffffu, v, 16);
                if (g == 0) atomicAdd(&s_col[wcol * 32 + nt * 8 + tg * 2 + e], v);
            }
        }

        __syncthreads();

        if (have_next && In != I) {
            prefetch_tile(As_s, g_fh + (size_t)In * TILE * D, tid);
            CP_COMMIT();
        }

        if (tid < TILE) atomicAdd(&g_suffix[I * TILE + tid], s_row[tid]);
        else            atomicAdd(&g_prefix[J * TILE + tid - TILE], s_col[tid - TILE]);

        buf ^= 1;
    }

    // ===== Phase 2: last CTA computes the lse reduction and the output =====
    __shared__ unsigned s_isLast;
    __shared__ float red[256];
    if (tid == 0) {
        __threadfence();
        unsigned old = atomicAdd(&g_sync2, 1u);
        s_isLast = (old == NCTA - 1) ? 1u : 0u;
    }
    __syncthreads();
    if (!s_isLast) return;

    __threadfence();   // acquire: all other CTAs' atomics now visible

    float local = 0.0f;
    for (int r = tid; r < N - 1; r += 256)
        local += __logf(g_suffix[r] + g_prefix[r + 1]) - g_pos[r];
    red[tid] = local;
    __syncthreads();
    for (int s = 128; s > 0; s >>= 1) {
        if (tid < s) red[tid] += red[tid + s];
        __syncthreads();
    }
    if (tid == 0) {
        out[0] = -WEIGHT * (red[0] / (float)N);
        g_sync1 = 0;   // reset for next graph replay
        g_sync2 = 0;
    }
}

// ---------------------------------------------------------------------------
extern "C" void kernel_launch(void* const* d_in, const int* in_sizes, int n_in,
                              void* d_out, int out_size) {
    const float* factor = (const float*)d_in[0];
    (void)in_sizes; (void)n_in; (void)out_size;

    cudaFuncSetAttribute(fused_kernel,
                         cudaFuncAttributeMaxDynamicSharedMemorySize, SMEM_BYTES);

    fused_kernel<<<NCTA, 256, SMEM_BYTES>>>(factor, (float*)d_out);
}

// round 9
// speedup vs baseline: 1.0320x; 1.0320x over previous
#include <cuda_runtime.h>
#include <cuda_fp16.h>
#include <cstdint>
#include <stdint.h>
#include <math.h>

#define N 8192
#define D 128
#define TILE 128
#define NB (N / TILE)             // 64
#define NTRI (NB * (NB + 1) / 2)  // 2080 upper-tri tiles
#define NCTA 296                  // 148 SMs x 2 resident CTAs
#define LDH 136                   // padded SMEM stride, LDSM conflict-free
#define WEIGHT 0.01f

// ---------------------------------------------------------------------------
// Device scratch
// ---------------------------------------------------------------------------
__device__ __half g_fh[N * D];
__device__ float  g_suffix[N];
__device__ float  g_prefix[N];
__device__ float  g_pos[N];
__device__ float  g_partial[32];

// ---------------------------------------------------------------------------
__device__ __forceinline__ void mma16816(float* c,
    uint32_t a0, uint32_t a1, uint32_t a2, uint32_t a3,
    uint32_t b0, uint32_t b1)
{
    asm volatile(
        "mma.sync.aligned.m16n8k16.row.col.f32.f16.f16.f32 "
        "{%0,%1,%2,%3}, {%4,%5,%6,%7}, {%8,%9}, {%0,%1,%2,%3};"
        : "+f"(c[0]), "+f"(c[1]), "+f"(c[2]), "+f"(c[3])
        : "r"(a0), "r"(a1), "r"(a2), "r"(a3), "r"(b0), "r"(b1));
}

__device__ __forceinline__ void ldsm_x4(uint32_t& r0, uint32_t& r1,
                                        uint32_t& r2, uint32_t& r3, uint32_t a) {
    asm volatile("ldmatrix.sync.aligned.m8n8.x4.shared.b16 {%0,%1,%2,%3}, [%4];"
                 : "=r"(r0), "=r"(r1), "=r"(r2), "=r"(r3) : "r"(a));
}
__device__ __forceinline__ void ldsm_x2(uint32_t& r0, uint32_t& r1, uint32_t a) {
    asm volatile("ldmatrix.sync.aligned.m8n8.x2.shared.b16 {%0,%1}, [%2];"
                 : "=r"(r0), "=r"(r1) : "r"(a));
}

__device__ __forceinline__ uint32_t smem_u32(const void* p) {
    uint32_t a;
    asm("{ .reg .u64 t; cvta.to.shared.u64 t, %1; cvt.u32.u64 %0, t; }"
        : "=r"(a) : "l"(p));
    return a;
}

#define CP_COMMIT()   asm volatile("cp.async.commit_group;" ::: "memory")
#define CP_WAIT_ALL() asm volatile("cp.async.wait_all;" ::: "memory")

__device__ __forceinline__ void prefetch_tile(uint32_t dst_s,
                                              const __half* __restrict__ src,
                                              int tid) {
#pragma unroll
    for (int it = 0; it < 8; it++) {
        int idx = tid + it * 256;
        int row = idx >> 4;
        int ch  = idx & 15;
        uint32_t d = dst_s + (uint32_t)(row * LDH + ch * 8) * 2u;
        const void* s = src + row * D + ch * 8;
        asm volatile("cp.async.cg.shared.global [%0], [%1], 16;"
                     :: "r"(d), "l"(s) : "memory");
    }
}

// ---------------------------------------------------------------------------
// Kernel 1: L2-normalize rows -> fp16; zero accumulators.
// ---------------------------------------------------------------------------
__global__ void normalize_kernel(const float* __restrict__ in) {
    int gw   = (blockIdx.x * blockDim.x + threadIdx.x) >> 5;
    int lane = threadIdx.x & 31;
    if (gw >= N) return;
    float4 v = ((const float4*)(in + (size_t)gw * D))[lane];
    float ss = v.x * v.x + v.y * v.y + v.z * v.z + v.w * v.w;
#pragma unroll
    for (int o = 16; o > 0; o >>= 1) ss += __shfl_xor_sync(0xffffffffu, ss, o);
    float scale = 1.0f / fmaxf(sqrtf(ss), 1e-12f);
    __half2 h0 = __floats2half2_rn(v.x * scale, v.y * scale);
    __half2 h1 = __floats2half2_rn(v.z * scale, v.w * scale);
    ((__half2*)(g_fh + (size_t)gw * D))[lane * 2 + 0] = h0;
    ((__half2*)(g_fh + (size_t)gw * D))[lane * 2 + 1] = h1;
    if (lane == 0) { g_suffix[gw] = 0.0f; g_prefix[gw] = 0.0f; }
}

// ---------------------------------------------------------------------------
// Kernel 2: persistent gram; LDSM-hoisted mainloop; fused exp epilogue.
// ---------------------------------------------------------------------------
#define SMEM_BYTES (TILE * LDH * 2 + 2 * TILE * LDH * 2 + 2 * TILE * 4)

__global__ __launch_bounds__(256, 2) void gram_mma_kernel() {
    extern __shared__ char smem[];
    __half* As  = (__half*)smem;
    __half* Bs0 = As + TILE * LDH;
    __half* Bs1 = Bs0 + TILE * LDH;
    float*  s_row = (float*)(Bs1 + TILE * LDH);
    float*  s_col = s_row + TILE;

    const int tid  = threadIdx.x;
    const int wid  = tid >> 5;
    const int lane = tid & 31;
    const int wrow = wid >> 2;
    const int wcol = wid & 3;
    const int g    = lane >> 2;
    const int tg   = lane & 3;

    const uint32_t As_s  = smem_u32(As);
    const uint32_t Bs_s0 = smem_u32(Bs0);
    const uint32_t Bs_s1 = smem_u32(Bs1);

    const uint32_t aoff = (uint32_t)((lane & 15) * LDH + (lane >> 4) * 8) * 2u;
    const uint32_t boff = (uint32_t)((lane & 7) * LDH + ((lane >> 3) & 1) * 8) * 2u;

    const int lo = (int)(((long long)blockIdx.x * NTRI) / NCTA);
    const int hi = (int)(((long long)(blockIdx.x + 1) * NTRI) / NCTA);

    int I = 0;
    while ((I + 1) * NB - (I + 1) * I / 2 <= lo) ++I;
    {
        const int J0 = I + (lo - (I * NB - I * (I - 1) / 2));
        prefetch_tile(As_s, g_fh + (size_t)I * TILE * D, tid);
        prefetch_tile(Bs_s0, g_fh + (size_t)J0 * TILE * D, tid);
        CP_COMMIT();
    }

    int buf = 0;
    for (int t = lo; t < hi; ++t) {
        while ((I + 1) * NB - (I + 1) * I / 2 <= t) ++I;
        const int J = I + (t - (I * NB - I * (I - 1) / 2));

        int In = I, Jn = 0;
        const bool have_next = (t + 1 < hi);
        if (have_next) {
            while ((In + 1) * NB - (In + 1) * In / 2 <= t + 1) ++In;
            Jn = In + ((t + 1) - (In * NB - In * (In - 1) / 2));
        }

        // Previous tile's end-sync guarantees staging reads are done.
        if (tid < TILE) s_row[tid] = 0.0f;
        else            s_col[tid - TILE] = 0.0f;

        CP_WAIT_ALL();
        __syncthreads();          // tiles ready + staging zeroed, both visible

        if (have_next) {
            prefetch_tile(buf ? Bs_s0 : Bs_s1, g_fh + (size_t)Jn * TILE * D, tid);
            CP_COMMIT();
        }

        const uint32_t Acur = As_s + aoff;
        const uint32_t Bcur = (buf ? Bs_s1 : Bs_s0) + boff;

        float acc[4][4][4];
#pragma unroll
        for (int mt = 0; mt < 4; mt++)
#pragma unroll
            for (int nt = 0; nt < 4; nt++)
#pragma unroll
                for (int e = 0; e < 4; e++) acc[mt][nt][e] = 0.0f;

#pragma unroll
        for (int k0 = 0; k0 < D; k0 += 16) {
            // Hoist ALL fragment loads: 4x ldsm_x2 (B) + 4x ldsm_x4 (A),
            // then 16 back-to-back MMAs. First MMAs consume the earliest
            // LDSM results, hiding the ~29cyc LDS latency.
            uint32_t bfr[4][2];
            uint32_t afr[4][4];
#pragma unroll
            for (int nt = 0; nt < 4; nt++)
                ldsm_x2(bfr[nt][0], bfr[nt][1],
                        Bcur + (uint32_t)((wcol * 32 + nt * 8) * LDH + k0) * 2u);
#pragma unroll
            for (int mt = 0; mt < 4; mt++)
                ldsm_x4(afr[mt][0], afr[mt][1], afr[mt][2], afr[mt][3],
                        Acur + (uint32_t)((wrow * 64 + mt * 16) * LDH + k0) * 2u);
#pragma unroll
            for (int mt = 0; mt < 4; mt++)
#pragma unroll
                for (int nt = 0; nt < 4; nt++)
                    mma16816(acc[mt][nt], afr[mt][0], afr[mt][1],
                             afr[mt][2], afr[mt][3], bfr[nt][0], bfr[nt][1]);
        }

        // --- Epilogue ---
        float csum[4][2];
#pragma unroll
        for (int nt = 0; nt < 4; nt++) { csum[nt][0] = 0.0f; csum[nt][1] = 0.0f; }

        if (J > I + 1) {
#pragma unroll
            for (int mt = 0; mt < 4; mt++) {
                float rs0 = 0.0f, rs1 = 0.0f;
#pragma unroll
                for (int nt = 0; nt < 4; nt++) {
                    float e00 = __expf(acc[mt][nt][0]);
                    float e01 = __expf(acc[mt][nt][1]);
                    float e10 = __expf(acc[mt][nt][2]);
                    float e11 = __expf(acc[mt][nt][3]);
                    rs0 += e00 + e01;
                    rs1 += e10 + e11;
                    csum[nt][0] += e00 + e10;
                    csum[nt][1] += e01 + e11;
                }
                rs0 += __shfl_xor_sync(0xffffffffu, rs0, 1);
                rs0 += __shfl_xor_sync(0xffffffffu, rs0, 2);
                rs1 += __shfl_xor_sync(0xffffffffu, rs1, 1);
                rs1 += __shfl_xor_sync(0xffffffffu, rs1, 2);
                if (tg == 0) {
                    atomicAdd(&s_row[wrow * 64 + mt * 16 + g], rs0);
                    atomicAdd(&s_row[wrow * 64 + mt * 16 + g + 8], rs1);
                }
            }
        } else {
#pragma unroll
            for (int mt = 0; mt < 4; mt++) {
                const int gi0 = I * TILE + wrow * 64 + mt * 16 + g;
                const int gi1 = gi0 + 8;
                float rs0 = 0.0f, rs1 = 0.0f;
#pragma unroll
                for (int nt = 0; nt < 4; nt++) {
                    const int gj0 = J * TILE + wcol * 32 + nt * 8 + tg * 2;
                    const int gj1 = gj0 + 1;
                    float e00 = (gj0 > gi0) ? __expf(acc[mt][nt][0]) : 0.0f;
                    float e01 = (gj1 > gi0) ? __expf(acc[mt][nt][1]) : 0.0f;
                    float e10 = (gj0 > gi1) ? __expf(acc[mt][nt][2]) : 0.0f;
                    float e11 = (gj1 > gi1) ? __expf(acc[mt][nt][3]) : 0.0f;
                    rs0 += e00 + e01;
                    rs1 += e10 + e11;
                    csum[nt][0] += ((gj0 >= gi0 + 2) ? e00 : 0.0f) + ((gj0 >= gi1 + 2) ? e10 : 0.0f);
                    csum[nt][1] += ((gj1 >= gi0 + 2) ? e01 : 0.0f) + ((gj1 >= gi1 + 2) ? e11 : 0.0f);
                    if (gj0 == gi0 + 1) g_pos[gi0] = acc[mt][nt][0];
                    if (gj1 == gi0 + 1) g_pos[gi0] = acc[mt][nt][1];
                    if (gj0 == gi1 + 1) g_pos[gi1] = acc[mt][nt][2];
                    if (gj1 == gi1 + 1) g_pos[gi1] = acc[mt][nt][3];
                }
                rs0 += __shfl_xor_sync(0xffffffffu, rs0, 1);
                rs0 += __shfl_xor_sync(0xffffffffu, rs0, 2);
                rs1 += __shfl_xor_sync(0xffffffffu, rs1, 1);
                rs1 += __shfl_xor_sync(0xffffffffu, rs1, 2);
                if (tg == 0) {
                    atomicAdd(&s_row[wrow * 64 + mt * 16 + g], rs0);
                    atomicAdd(&s_row[wrow * 64 + mt * 16 + g + 8], rs1);
                }
            }
        }

#pragma unroll
        for (int nt = 0; nt < 4; nt++) {
#pragma unroll
            for (int e = 0; e < 2; e++) {
                float v = csum[nt][e];
                v += __shfl_xor_sync(0xffffffffu, v, 4);
                v += __shfl_xor_sync(0xffffffffu, v, 8);
                v += __shfl_xor_sync(0xffffffffu, v, 16);
                if (g == 0) atomicAdd(&s_col[wcol * 32 + nt * 8 + tg * 2 + e], v);
            }
        }

        __syncthreads();          // epilogue staging complete; As reads done

        if (have_next && In != I) {
            prefetch_tile(As_s, g_fh + (size_t)In * TILE * D, tid);
            CP_COMMIT();
        }

        if (tid < TILE) atomicAdd(&g_suffix[I * TILE + tid], s_row[tid]);
        else            atomicAdd(&g_prefix[J * TILE + tid - TILE], s_col[tid - TILE]);

        buf ^= 1;
    }
}

// ---------------------------------------------------------------------------
// Kernel 3a/3b: parallel (lse - pos) partials, then fold.
// ---------------------------------------------------------------------------
__global__ void finish_partial_kernel() {
    __shared__ float red[256];
    int t = threadIdx.x;
    int r = blockIdx.x * 256 + t;
    float local = 0.0f;
    if (r < N - 1)
        local = __logf(g_suffix[r] + g_prefix[r + 1]) - g_pos[r];
    red[t] = local;
    __syncthreads();
    for (int s = 128; s > 0; s >>= 1) {
        if (t < s) red[t] += red[t + s];
        __syncthreads();
    }
    if (t == 0) g_partial[blockIdx.x] = red[0];
}

__global__ void finish_final_kernel(float* __restrict__ out) {
    int t = threadIdx.x;
    float v = g_partial[t];
#pragma unroll
    for (int o = 16; o > 0; o >>= 1) v += __shfl_xor_sync(0xffffffffu, v, o);
    if (t == 0) out[0] = -WEIGHT * (v / (float)N);
}

// ---------------------------------------------------------------------------
extern "C" void kernel_launch(void* const* d_in, const int* in_sizes, int n_in,
                              void* d_out, int out_size) {
    const float* factor = (const float*)d_in[0];
    (void)in_sizes; (void)n_in; (void)out_size;

    static bool attr_set = false;
    if (!attr_set) {
        cudaFuncSetAttribute(gram_mma_kernel,
                             cudaFuncAttributeMaxDynamicSharedMemorySize, SMEM_BYTES);
        attr_set = true;
    }

    normalize_kernel<<<(N * 32) / 256, 256>>>(factor);
    gram_mma_kernel<<<NCTA, 256, SMEM_BYTES>>>();
    finish_partial_kernel<<<32, 256>>>();
    finish_final_kernel<<<1, 32>>>((float*)d_out);
}